// round 1
// baseline (speedup 1.0000x reference)
#include <cuda_runtime.h>
#include <math.h>
#include <stdint.h>

// ---------------- scratch (device globals; no allocations) ----------------
// sized for the protein branch (N=76800, F3=216); mol branch reuses them.
#define MAXNF (76800u * 216u)
__device__ float g_h_buf [MAXNF];
__device__ float g_agg_buf[MAXNF];
__device__ float g_xa_buf [MAXNF];
__device__ float g_xb_buf [MAXNF];
__device__ float g_norm_buf[76800];
__device__ float g_cnt_buf[256];
__device__ float g_pool_buf[256 * 312];
__device__ float g_fc1_buf[256 * 1024];
__device__ float g_cat_buf[256 * 256];
__device__ float g_head_buf[256 * 512];

// ---------------- elementwise kernels ----------------
__global__ void k_zero(float* p, int n) {
    int i = blockIdx.x * blockDim.x + threadIdx.x;
    if (i < n) p[i] = 0.f;
}

__global__ void k_count(const int* __restrict__ idx, float* __restrict__ acc, int n) {
    int i = blockIdx.x * blockDim.x + threadIdx.x;
    if (i < n) atomicAdd(&acc[idx[i]], 1.f);
}

__global__ void k_rsqrt1(float* p, int n) {
    int i = blockIdx.x * blockDim.x + threadIdx.x;
    if (i < n) p[i] = rsqrtf(p[i] + 1.f);
}

// agg[dst] += h[src] * norm[src], one warp per edge
__global__ void k_scatter(const float* __restrict__ h, const float* __restrict__ nrm,
                          const int* __restrict__ src, const int* __restrict__ dst,
                          float* __restrict__ agg, int E, int F) {
    int warp = (blockIdx.x * blockDim.x + threadIdx.x) >> 5;
    int lane = threadIdx.x & 31;
    if (warp >= E) return;
    int s = src[warp];
    int d = dst[warp];
    float ns = nrm[s];
    const float* hs = h + (size_t)s * F;
    float* ad = agg + (size_t)d * F;
    for (int f = lane; f < F; f += 32)
        atomicAdd(&ad[f], hs[f] * ns);
}

// out = relu(norm_i * (agg + norm_i * h) + bias[f])
__global__ void k_combine(const float* __restrict__ h, const float* __restrict__ agg,
                          const float* __restrict__ nrm, const float* __restrict__ bias,
                          float* __restrict__ out, int N, int F) {
    int idx = blockIdx.x * blockDim.x + threadIdx.x;
    if (idx >= N * F) return;
    int i = idx / F;
    int f = idx - i * F;
    float nn = nrm[i];
    float v = nn * (agg[idx] + nn * h[idx]) + bias[f];
    out[idx] = fmaxf(v, 0.f);
}

// pool[batch[i]*F + f] += x[i*F + f]
__global__ void k_poolsum(const float* __restrict__ x, const int* __restrict__ bat,
                          float* __restrict__ pool, int N, int F) {
    int idx = blockIdx.x * blockDim.x + threadIdx.x;
    if (idx >= N * F) return;
    int i = idx / F;
    int f = idx - i * F;
    atomicAdd(&pool[(size_t)bat[i] * F + f], x[idx]);
}

__global__ void k_pooldiv(float* __restrict__ pool, const float* __restrict__ cnt, int B, int F) {
    int idx = blockIdx.x * blockDim.x + threadIdx.x;
    if (idx >= B * F) return;
    int g = idx / F;
    pool[idx] = pool[idx] / fmaxf(cnt[g], 1.f);
}

// ---------------- SGEMM: C[N,M] = A[N,K] @ W[K,M] (+bias, opt relu), ldc-aware ----------------
#define BM 128
#define BN 128
#define BKK 8

__global__ __launch_bounds__(256) void k_sgemm(
    const float* __restrict__ A, const float* __restrict__ W,
    const float* __restrict__ bias, float* __restrict__ C,
    int N, int K, int M, int ldc, int relu)
{
    __shared__ float As[BKK][BM];
    __shared__ float Bs[BKK][BN];

    int tid = threadIdx.x;
    int row0 = blockIdx.y * BM;
    int col0 = blockIdx.x * BN;
    int tx = tid & 15;        // 0..15 -> 8 cols each
    int ty = tid >> 4;        // 0..15 -> 8 rows each

    float acc[8][8];
#pragma unroll
    for (int i = 0; i < 8; i++)
#pragma unroll
        for (int j = 0; j < 8; j++) acc[i][j] = 0.f;

    // A tile load mapping: 128x8 elems, 4 per thread
    int a_r = tid >> 1;            // 0..127
    int a_c = (tid & 1) * 4;       // 0 or 4
    // B tile load mapping: 8x128 elems, 4 per thread
    int b_r = tid >> 5;            // 0..7
    int b_c = (tid & 31) * 4;      // 0..124

    for (int k0 = 0; k0 < K; k0 += BKK) {
        int ar = row0 + a_r;
#pragma unroll
        for (int i = 0; i < 4; i++) {
            int kc = k0 + a_c + i;
            As[a_c + i][a_r] = (ar < N && kc < K) ? A[(size_t)ar * K + kc] : 0.f;
        }
        int br = k0 + b_r;
#pragma unroll
        for (int i = 0; i < 4; i++) {
            int bc = col0 + b_c + i;
            Bs[b_r][b_c + i] = (br < K && bc < M) ? W[(size_t)br * M + bc] : 0.f;
        }
        __syncthreads();

#pragma unroll
        for (int kk = 0; kk < BKK; kk++) {
            float af[8], bf[8];
#pragma unroll
            for (int i = 0; i < 8; i++) af[i] = As[kk][ty * 8 + i];
#pragma unroll
            for (int j = 0; j < 8; j++) bf[j] = Bs[kk][tx * 8 + j];
#pragma unroll
            for (int i = 0; i < 8; i++)
#pragma unroll
                for (int j = 0; j < 8; j++) acc[i][j] += af[i] * bf[j];
        }
        __syncthreads();
    }

#pragma unroll
    for (int i = 0; i < 8; i++) {
        int r = row0 + ty * 8 + i;
        if (r >= N) continue;
#pragma unroll
        for (int j = 0; j < 8; j++) {
            int c = col0 + tx * 8 + j;
            if (c >= M) continue;
            float v = acc[i][j] + (bias ? bias[c] : 0.f);
            if (relu) v = fmaxf(v, 0.f);
            C[(size_t)r * ldc + c] = v;
        }
    }
}

// ---------------- host orchestration ----------------
static inline int gdiv(int n, int d) { return (n + d - 1) / d; }

static void launch_sgemm(const float* A, const float* W, const float* bias, float* C,
                         int N, int K, int M, int ldc, int relu) {
    dim3 grid(gdiv(M, BN), gdiv(N, BM));
    k_sgemm<<<grid, 256>>>(A, W, bias, C, N, K, M, ldc, relu);
}

static void run_branch(const float* x0, const int* ei, int E, const int* bat, int N,
                       int F0, int F1, int F2, int F3,
                       const float* w1, const float* b1,
                       const float* w2, const float* b2,
                       const float* w3, const float* b3,
                       const float* fw1, const float* fb1,
                       const float* fw2, const float* fb2,
                       float* cat_ptr,
                       float* h, float* agg, float* xa, float* xb,
                       float* nrm, float* cnt, float* pool, float* fc1)
{
    const int* src = ei;
    const int* dst = ei + E;
    const int T = 256;

    // norm = rsqrt(indeg(dst) + 1)
    k_zero<<<gdiv(N, T), T>>>(nrm, N);
    k_count<<<gdiv(E, T), T>>>(dst, nrm, E);
    k_rsqrt1<<<gdiv(N, T), T>>>(nrm, N);

    // per-graph node counts
    k_zero<<<1, 256>>>(cnt, 256);
    k_count<<<gdiv(N, T), T>>>(bat, cnt, N);

    const float* xin = x0;
    int Fin = F0;
    const float* Ws[3] = {w1, w2, w3};
    const float* Bb[3] = {b1, b2, b3};
    int Fo[3] = {F1, F2, F3};
    float* outs[3] = {xa, xb, xa};

    for (int l = 0; l < 3; l++) {
        int Fout = Fo[l];
        // h = x @ W
        launch_sgemm(xin, Ws[l], nullptr, h, N, Fin, Fout, Fout, 0);
        // agg = segment_sum(h[src]*norm[src] -> dst)
        k_zero<<<gdiv(N * Fout, T), T>>>(agg, N * Fout);
        k_scatter<<<gdiv(E, 8), 256>>>(h, nrm, src, dst, agg, E, Fout);
        // out = relu(norm*(agg + norm*h) + b)
        k_combine<<<gdiv(N * Fout, T), T>>>(h, agg, nrm, Bb[l], outs[l], N, Fout);
        xin = outs[l];
        Fin = Fout;
    }

    // global mean pool -> [256, F3]
    k_zero<<<gdiv(256 * F3, T), T>>>(pool, 256 * F3);
    k_poolsum<<<gdiv(N * F3, T), T>>>(xin, bat, pool, N, F3);
    k_pooldiv<<<gdiv(256 * F3, T), T>>>(pool, cnt, 256, F3);

    // fc1 (relu), fc2 (no relu) -> write into concat buffer (ldc=256)
    launch_sgemm(pool, fw1, fb1, fc1, 256, F3, 1024, 1024, 1);
    launch_sgemm(fc1, fw2, fb2, cat_ptr, 256, 1024, 128, 256, 0);
}

extern "C" void kernel_launch(void* const* d_in, const int* in_sizes, int n_in,
                              void* d_out, int out_size)
{
    float *h, *agg, *xa, *xb, *nrm, *cnt, *pool, *fc1, *cat, *head;
    cudaGetSymbolAddress((void**)&h,    g_h_buf);
    cudaGetSymbolAddress((void**)&agg,  g_agg_buf);
    cudaGetSymbolAddress((void**)&xa,   g_xa_buf);
    cudaGetSymbolAddress((void**)&xb,   g_xb_buf);
    cudaGetSymbolAddress((void**)&nrm,  g_norm_buf);
    cudaGetSymbolAddress((void**)&cnt,  g_cnt_buf);
    cudaGetSymbolAddress((void**)&pool, g_pool_buf);
    cudaGetSymbolAddress((void**)&fc1,  g_fc1_buf);
    cudaGetSymbolAddress((void**)&cat,  g_cat_buf);
    cudaGetSymbolAddress((void**)&head, g_head_buf);

    const float* mol_x  = (const float*)d_in[0];
    const int*   mol_ei = (const int*)  d_in[1];
    const int*   mol_b  = (const int*)  d_in[2];
    const float* pro_x  = (const float*)d_in[3];
    const int*   pro_ei = (const int*)  d_in[4];
    const int*   pro_b  = (const int*)  d_in[5];

    int N_mol = in_sizes[2];
    int E_mol = in_sizes[1] / 2;
    int F_mol = in_sizes[0] / N_mol;     // 78
    int N_pro = in_sizes[5];
    int E_pro = in_sizes[4] / 2;
    int F_pro = in_sizes[3] / N_pro;     // 54

    const float* mw1  = (const float*)d_in[6];
    const float* mb1  = (const float*)d_in[7];
    const float* mw2  = (const float*)d_in[8];
    const float* mb2  = (const float*)d_in[9];
    const float* mw3  = (const float*)d_in[10];
    const float* mb3  = (const float*)d_in[11];
    const float* mfw1 = (const float*)d_in[12];
    const float* mfb1 = (const float*)d_in[13];
    const float* mfw2 = (const float*)d_in[14];
    const float* mfb2 = (const float*)d_in[15];
    const float* pw1  = (const float*)d_in[16];
    const float* pb1  = (const float*)d_in[17];
    const float* pw2  = (const float*)d_in[18];
    const float* pb2  = (const float*)d_in[19];
    const float* pw3  = (const float*)d_in[20];
    const float* pb3  = (const float*)d_in[21];
    const float* pfw1 = (const float*)d_in[22];
    const float* pfb1 = (const float*)d_in[23];
    const float* pfw2 = (const float*)d_in[24];
    const float* pfb2 = (const float*)d_in[25];
    const float* fc1w = (const float*)d_in[26];
    const float* fc1b = (const float*)d_in[27];
    const float* fc2w = (const float*)d_in[28];
    const float* fc2b = (const float*)d_in[29];
    const float* outw = (const float*)d_in[30];
    const float* outb = (const float*)d_in[31];

    // molecule branch: 78 -> 78 -> 156 -> 312; writes cat[:, 0:128]
    run_branch(mol_x, mol_ei, E_mol, mol_b, N_mol,
               F_mol, F_mol, 2 * F_mol, 4 * F_mol,
               mw1, mb1, mw2, mb2, mw3, mb3,
               mfw1, mfb1, mfw2, mfb2,
               cat,
               h, agg, xa, xb, nrm, cnt, pool, fc1);

    // protein branch: 54 -> 54 -> 108 -> 216; writes cat[:, 128:256]
    run_branch(pro_x, pro_ei, E_pro, pro_b, N_pro,
               F_pro, F_pro, 2 * F_pro, 4 * F_pro,
               pw1, pb1, pw2, pb2, pw3, pb3,
               pfw1, pfb1, pfw2, pfb2,
               cat + 128,
               h, agg, xa, xb, nrm, cnt, pool, fc1);

    // combined head: [256,256] -> 1024 (relu) -> 512 (relu) -> 1
    launch_sgemm(cat,  fc1w, fc1b, fc1,           256, 256,  1024, 1024, 1);
    launch_sgemm(fc1,  fc2w, fc2b, head,          256, 1024, 512,  512,  1);
    launch_sgemm(head, outw, outb, (float*)d_out, 256, 512,  1,    1,    0);
}

// round 2
// speedup vs baseline: 1.2590x; 1.2590x over previous
#include <cuda_runtime.h>
#include <math.h>
#include <stdint.h>

// ---------------- scratch (device globals; no allocations) ----------------
#define MAXN 76800
#define MAXE 768000
#define MAXNF (76800u * 216u)

__device__ float g_Y[MAXNF];     // aggregated input per layer
__device__ float g_A[MAXNF];     // layer output ping
__device__ float g_B[MAXNF];     // layer output pong
__device__ float g_nrm[MAXN];
__device__ int   g_deg[MAXN];
__device__ int   g_cur[MAXN];
__device__ int   g_rowptr[MAXN + 1];
__device__ int   g_csr[MAXE];
__device__ int   g_gcnt[256];
__device__ int   g_gptr[257];
__device__ float g_pool[256 * 312];
__device__ float g_fc1[256 * 1024];
__device__ float g_cat[256 * 256];
__device__ float g_head[256 * 512];

static inline int gdiv(int n, int d) { return (n + d - 1) / d; }

// ---------------- small utility kernels ----------------
__global__ void k_zero2i(int* a, int* b, int n) {
    int i = blockIdx.x * blockDim.x + threadIdx.x;
    if (i < n) { a[i] = 0; b[i] = 0; }
}

__global__ void k_zeroi(int* a, int n) {
    int i = blockIdx.x * blockDim.x + threadIdx.x;
    if (i < n) a[i] = 0;
}

__global__ void k_hist(const int* __restrict__ idx, int* __restrict__ acc, int n) {
    int i = blockIdx.x * blockDim.x + threadIdx.x;
    if (i < n) atomicAdd(&acc[idx[i]], 1);
}

__global__ void k_nrm(const int* __restrict__ deg, float* __restrict__ nrm, int n) {
    int i = blockIdx.x * blockDim.x + threadIdx.x;
    if (i < n) nrm[i] = rsqrtf((float)deg[i] + 1.f);
}

// single-block exclusive scan (n up to ~100k), out[n] = total
__global__ void k_scan_ex(const int* __restrict__ in, int* __restrict__ out, int n) {
    __shared__ int wsum[32];
    __shared__ int carry_s;
    int tid = threadIdx.x;
    int lane = tid & 31, wid = tid >> 5;
    if (tid == 0) carry_s = 0;
    __syncthreads();
    for (int base = 0; base < n; base += 1024) {
        int i = base + tid;
        int v = (i < n) ? in[i] : 0;
        int s = v;
#pragma unroll
        for (int off = 1; off < 32; off <<= 1) {
            int t = __shfl_up_sync(0xffffffffu, s, off);
            if (lane >= off) s += t;
        }
        if (lane == 31) wsum[wid] = s;
        __syncthreads();
        if (wid == 0) {
            int ws = wsum[lane];
#pragma unroll
            for (int off = 1; off < 32; off <<= 1) {
                int t = __shfl_up_sync(0xffffffffu, ws, off);
                if (lane >= off) ws += t;
            }
            wsum[lane] = ws;
        }
        __syncthreads();
        int wofs = (wid > 0) ? wsum[wid - 1] : 0;
        int incl = carry_s + wofs + s;
        if (i < n) out[i] = incl - v;
        __syncthreads();
        if (tid == 1023) carry_s = incl;
        __syncthreads();
    }
    if (threadIdx.x == 0) out[n] = carry_s;
}

__global__ void k_fill(const int* __restrict__ src, const int* __restrict__ dst,
                       const int* __restrict__ rowptr, int* __restrict__ cur,
                       int* __restrict__ csr, int E) {
    int e = blockIdx.x * blockDim.x + threadIdx.x;
    if (e >= E) return;
    int d = dst[e];
    int p = rowptr[d] + atomicAdd(&cur[d], 1);
    csr[p] = src[e];
}

// ---------------- fused aggregation: y_i = nrm_i*(sum_{e->i} nrm_s x_s + nrm_i x_i) ----
template <int NF>
__global__ void k_agg(const float* __restrict__ x, const float* __restrict__ nrm,
                      const int* __restrict__ rowptr, const int* __restrict__ csr,
                      float* __restrict__ y, int N, int F) {
    int warp = (blockIdx.x * blockDim.x + threadIdx.x) >> 5;
    int lane = threadIdx.x & 31;
    if (warp >= N) return;
    int beg = rowptr[warp], end = rowptr[warp + 1];
    float ni = nrm[warp];

    float acc[NF];
#pragma unroll
    for (int j = 0; j < NF; j++) acc[j] = 0.f;

    int e = beg;
    for (; e + 1 < end; e += 2) {
        int s0 = csr[e], s1 = csr[e + 1];
        float n0 = nrm[s0], n1 = nrm[s1];
        const float* x0 = x + (size_t)s0 * F;
        const float* x1 = x + (size_t)s1 * F;
#pragma unroll
        for (int j = 0; j < NF; j++) {
            int f = lane + 32 * j;
            if (f < F) acc[j] += x0[f] * n0 + x1[f] * n1;
        }
    }
    if (e < end) {
        int s0 = csr[e];
        float n0 = nrm[s0];
        const float* x0 = x + (size_t)s0 * F;
#pragma unroll
        for (int j = 0; j < NF; j++) {
            int f = lane + 32 * j;
            if (f < F) acc[j] += x0[f] * n0;
        }
    }
    const float* xi = x + (size_t)warp * F;
    float* yi = y + (size_t)warp * F;
#pragma unroll
    for (int j = 0; j < NF; j++) {
        int f = lane + 32 * j;
        if (f < F) yi[f] = ni * (acc[j] + ni * xi[f]);
    }
}

static void launch_agg(const float* x, const float* nrm, const int* rp, const int* csr,
                       float* y, int N, int F) {
    int blocks = gdiv(N, 8);  // 8 warps / 256-thread block
    int nf = (F + 31) / 32;
    switch (nf) {
        case 2: k_agg<2><<<blocks, 256>>>(x, nrm, rp, csr, y, N, F); break;
        case 3: k_agg<3><<<blocks, 256>>>(x, nrm, rp, csr, y, N, F); break;
        case 4: k_agg<4><<<blocks, 256>>>(x, nrm, rp, csr, y, N, F); break;
        case 5: k_agg<5><<<blocks, 256>>>(x, nrm, rp, csr, y, N, F); break;
        default: k_agg<8><<<blocks, 256>>>(x, nrm, rp, csr, y, N, F); break;
    }
}

// ---------------- mean pool over contiguous per-graph ranges ----------------
__global__ void k_pool(const float* __restrict__ x, const int* __restrict__ gptr,
                       float* __restrict__ pool, int F) {
    int g = blockIdx.x;
    int beg = gptr[g], end = gptr[g + 1];
    float inv = 1.f / fmaxf((float)(end - beg), 1.f);
    for (int f = threadIdx.x; f < F; f += blockDim.x) {
        float s0 = 0.f, s1 = 0.f, s2 = 0.f, s3 = 0.f;
        int i = beg;
        for (; i + 3 < end; i += 4) {
            s0 += x[(size_t)(i + 0) * F + f];
            s1 += x[(size_t)(i + 1) * F + f];
            s2 += x[(size_t)(i + 2) * F + f];
            s3 += x[(size_t)(i + 3) * F + f];
        }
        for (; i < end; i++) s0 += x[(size_t)i * F + f];
        pool[(size_t)g * F + f] = (s0 + s1 + s2 + s3) * inv;
    }
}

// ---------------- SGEMM: C[N,M] = A[N,K] @ W[K,M] (+bias, opt relu), ldc-aware ----------------
#define BM 128
#define BN 128
#define BKK 8

__global__ __launch_bounds__(256) void k_sgemm(
    const float* __restrict__ A, const float* __restrict__ W,
    const float* __restrict__ bias, float* __restrict__ C,
    int N, int K, int M, int ldc, int relu)
{
    __shared__ float As[BKK][BM];
    __shared__ float Bs[BKK][BN];

    int tid = threadIdx.x;
    int row0 = blockIdx.y * BM;
    int col0 = blockIdx.x * BN;
    int tx = tid & 15;
    int ty = tid >> 4;

    float acc[8][8];
#pragma unroll
    for (int i = 0; i < 8; i++)
#pragma unroll
        for (int j = 0; j < 8; j++) acc[i][j] = 0.f;

    int a_r = tid >> 1;
    int a_c = (tid & 1) * 4;
    int b_r = tid >> 5;
    int b_c = (tid & 31) * 4;

    for (int k0 = 0; k0 < K; k0 += BKK) {
        int ar = row0 + a_r;
#pragma unroll
        for (int i = 0; i < 4; i++) {
            int kc = k0 + a_c + i;
            As[a_c + i][a_r] = (ar < N && kc < K) ? A[(size_t)ar * K + kc] : 0.f;
        }
        int br = k0 + b_r;
#pragma unroll
        for (int i = 0; i < 4; i++) {
            int bc = col0 + b_c + i;
            Bs[b_r][b_c + i] = (br < K && bc < M) ? W[(size_t)br * M + bc] : 0.f;
        }
        __syncthreads();

#pragma unroll
        for (int kk = 0; kk < BKK; kk++) {
            float af[8], bf[8];
#pragma unroll
            for (int i = 0; i < 8; i++) af[i] = As[kk][ty * 8 + i];
#pragma unroll
            for (int j = 0; j < 8; j++) bf[j] = Bs[kk][tx * 8 + j];
#pragma unroll
            for (int i = 0; i < 8; i++)
#pragma unroll
                for (int j = 0; j < 8; j++) acc[i][j] += af[i] * bf[j];
        }
        __syncthreads();
    }

#pragma unroll
    for (int i = 0; i < 8; i++) {
        int r = row0 + ty * 8 + i;
        if (r >= N) continue;
#pragma unroll
        for (int j = 0; j < 8; j++) {
            int c = col0 + tx * 8 + j;
            if (c >= M) continue;
            float v = acc[i][j] + (bias ? bias[c] : 0.f);
            if (relu) v = fmaxf(v, 0.f);
            C[(size_t)r * ldc + c] = v;
        }
    }
}

static void launch_sgemm(const float* A, const float* W, const float* bias, float* C,
                         int N, int K, int M, int ldc, int relu) {
    dim3 grid(gdiv(M, BN), gdiv(N, BM));
    k_sgemm<<<grid, 256>>>(A, W, bias, C, N, K, M, ldc, relu);
}

// ---------------- branch orchestration ----------------
static void run_branch(const float* x0, const int* ei, int E, const int* bat, int N,
                       int F0, int F1, int F2, int F3,
                       const float* w1, const float* b1,
                       const float* w2, const float* b2,
                       const float* w3, const float* b3,
                       const float* fw1, const float* fb1,
                       const float* fw2, const float* fb2,
                       float* cat_ptr,
                       float* Y, float* A, float* Bf,
                       float* nrm, int* deg, int* cur, int* rowptr, int* csr,
                       int* gcnt, int* gptr, float* pool, float* fc1)
{
    const int* src = ei;
    const int* dst = ei + E;
    const int T = 256;

    // CSR by dst + norm
    k_zero2i<<<gdiv(N, T), T>>>(deg, cur, N);
    k_hist<<<gdiv(E, T), T>>>(dst, deg, E);
    k_scan_ex<<<1, 1024>>>(deg, rowptr, N);
    k_nrm<<<gdiv(N, T), T>>>(deg, nrm, N);
    k_fill<<<gdiv(E, T), T>>>(src, dst, rowptr, cur, csr, E);

    // layer 1: agg(x0) -> Y [N,F0]; out A = relu(Y@w1 + b1) [N,F1]
    launch_agg(x0, nrm, rowptr, csr, Y, N, F0);
    launch_sgemm(Y, w1, b1, A, N, F0, F1, F1, 1);

    // layer 2
    launch_agg(A, nrm, rowptr, csr, Y, N, F1);
    launch_sgemm(Y, w2, b2, Bf, N, F1, F2, F2, 1);

    // layer 3
    launch_agg(Bf, nrm, rowptr, csr, Y, N, F2);
    launch_sgemm(Y, w3, b3, A, N, F2, F3, F3, 1);

    // mean pool (batch is sorted -> contiguous ranges)
    k_zeroi<<<1, 256>>>(gcnt, 256);
    k_hist<<<gdiv(N, T), T>>>(bat, gcnt, N);
    k_scan_ex<<<1, 1024>>>(gcnt, gptr, 256);
    k_pool<<<256, 256>>>(A, gptr, pool, F3);

    // fc1 (relu), fc2 -> concat slice (ldc=256)
    launch_sgemm(pool, fw1, fb1, fc1, 256, F3, 1024, 1024, 1);
    launch_sgemm(fc1, fw2, fb2, cat_ptr, 256, 1024, 128, 256, 0);
}

extern "C" void kernel_launch(void* const* d_in, const int* in_sizes, int n_in,
                              void* d_out, int out_size)
{
    float *Y, *A, *Bf, *nrm, *pool, *fc1, *cat, *head;
    int *deg, *cur, *rowptr, *csr, *gcnt, *gptr;
    cudaGetSymbolAddress((void**)&Y,      g_Y);
    cudaGetSymbolAddress((void**)&A,      g_A);
    cudaGetSymbolAddress((void**)&Bf,     g_B);
    cudaGetSymbolAddress((void**)&nrm,    g_nrm);
    cudaGetSymbolAddress((void**)&deg,    g_deg);
    cudaGetSymbolAddress((void**)&cur,    g_cur);
    cudaGetSymbolAddress((void**)&rowptr, g_rowptr);
    cudaGetSymbolAddress((void**)&csr,    g_csr);
    cudaGetSymbolAddress((void**)&gcnt,   g_gcnt);
    cudaGetSymbolAddress((void**)&gptr,   g_gptr);
    cudaGetSymbolAddress((void**)&pool,   g_pool);
    cudaGetSymbolAddress((void**)&fc1,    g_fc1);
    cudaGetSymbolAddress((void**)&cat,    g_cat);
    cudaGetSymbolAddress((void**)&head,   g_head);

    const float* mol_x  = (const float*)d_in[0];
    const int*   mol_ei = (const int*)  d_in[1];
    const int*   mol_b  = (const int*)  d_in[2];
    const float* pro_x  = (const float*)d_in[3];
    const int*   pro_ei = (const int*)  d_in[4];
    const int*   pro_b  = (const int*)  d_in[5];

    int N_mol = in_sizes[2];
    int E_mol = in_sizes[1] / 2;
    int F_mol = in_sizes[0] / N_mol;     // 78
    int N_pro = in_sizes[5];
    int E_pro = in_sizes[4] / 2;
    int F_pro = in_sizes[3] / N_pro;     // 54

    const float* mw1  = (const float*)d_in[6];
    const float* mb1  = (const float*)d_in[7];
    const float* mw2  = (const float*)d_in[8];
    const float* mb2  = (const float*)d_in[9];
    const float* mw3  = (const float*)d_in[10];
    const float* mb3  = (const float*)d_in[11];
    const float* mfw1 = (const float*)d_in[12];
    const float* mfb1 = (const float*)d_in[13];
    const float* mfw2 = (const float*)d_in[14];
    const float* mfb2 = (const float*)d_in[15];
    const float* pw1  = (const float*)d_in[16];
    const float* pb1  = (const float*)d_in[17];
    const float* pw2  = (const float*)d_in[18];
    const float* pb2  = (const float*)d_in[19];
    const float* pw3  = (const float*)d_in[20];
    const float* pb3  = (const float*)d_in[21];
    const float* pfw1 = (const float*)d_in[22];
    const float* pfb1 = (const float*)d_in[23];
    const float* pfw2 = (const float*)d_in[24];
    const float* pfb2 = (const float*)d_in[25];
    const float* fc1w = (const float*)d_in[26];
    const float* fc1b = (const float*)d_in[27];
    const float* fc2w = (const float*)d_in[28];
    const float* fc2b = (const float*)d_in[29];
    const float* outw = (const float*)d_in[30];
    const float* outb = (const float*)d_in[31];

    // protein branch first (heavy): 54 -> 54 -> 108 -> 216; cat[:,128:256]
    run_branch(pro_x, pro_ei, E_pro, pro_b, N_pro,
               F_pro, F_pro, 2 * F_pro, 4 * F_pro,
               pw1, pb1, pw2, pb2, pw3, pb3,
               pfw1, pfb1, pfw2, pfb2,
               cat + 128,
               Y, A, Bf, nrm, deg, cur, rowptr, csr, gcnt, gptr, pool, fc1);

    // molecule branch: 78 -> 78 -> 156 -> 312; cat[:,0:128]
    run_branch(mol_x, mol_ei, E_mol, mol_b, N_mol,
               F_mol, F_mol, 2 * F_mol, 4 * F_mol,
               mw1, mb1, mw2, mb2, mw3, mb3,
               mfw1, mfb1, mfw2, mfb2,
               cat,
               Y, A, Bf, nrm, deg, cur, rowptr, csr, gcnt, gptr, pool, fc1);

    // combined head
    launch_sgemm(cat,  fc1w, fc1b, fc1,           256, 256,  1024, 1024, 1);
    launch_sgemm(fc1,  fc2w, fc2b, head,          256, 1024, 512,  512,  1);
    launch_sgemm(head, outw, outb, (float*)d_out, 256, 512,  1,    1,    0);
}

// round 3
// speedup vs baseline: 1.7586x; 1.3968x over previous
#include <cuda_runtime.h>
#include <math.h>
#include <stdint.h>

// ---------------- scratch (device globals; no allocations) ----------------
#define MAXN 76800
#define MAXE 768000
#define MAXNF (76800u * 216u)

__device__ float g_Y[MAXNF];
__device__ float g_A[MAXNF];
__device__ float g_B[MAXNF];
__device__ float g_nrm[MAXN];
__device__ int   g_deg[MAXN];
__device__ int   g_cur[MAXN];
__device__ int   g_rowptr[MAXN + 1];
__device__ int   g_csr[MAXE];
__device__ int   g_gcnt[256];
__device__ int   g_gptr[257];
__device__ float g_pool[256 * 312];
__device__ float g_fc1[256 * 1024];
__device__ float g_cat[256 * 256];
__device__ float g_head[256 * 512];

static inline int gdiv(int n, int d) { return (n + d - 1) / d; }

// ---------------- small utility kernels ----------------
__global__ void k_zero2i(int* a, int* b, int n) {
    int i = blockIdx.x * blockDim.x + threadIdx.x;
    if (i < n) { a[i] = 0; b[i] = 0; }
}

__global__ void k_zeroi(int* a, int n) {
    int i = blockIdx.x * blockDim.x + threadIdx.x;
    if (i < n) a[i] = 0;
}

__global__ void k_hist(const int* __restrict__ idx, int* __restrict__ acc, int n) {
    int i = blockIdx.x * blockDim.x + threadIdx.x;
    if (i < n) atomicAdd(&acc[idx[i]], 1);
}

__global__ void k_nrm(const int* __restrict__ deg, float* __restrict__ nrm, int n) {
    int i = blockIdx.x * blockDim.x + threadIdx.x;
    if (i < n) nrm[i] = rsqrtf((float)deg[i] + 1.f);
}

// single-block exclusive scan, out[n] = total
__global__ void k_scan_ex(const int* __restrict__ in, int* __restrict__ out, int n) {
    __shared__ int wsum[32];
    __shared__ int carry_s;
    int tid = threadIdx.x;
    int lane = tid & 31, wid = tid >> 5;
    if (tid == 0) carry_s = 0;
    __syncthreads();
    for (int base = 0; base < n; base += 1024) {
        int i = base + tid;
        int v = (i < n) ? in[i] : 0;
        int s = v;
#pragma unroll
        for (int off = 1; off < 32; off <<= 1) {
            int t = __shfl_up_sync(0xffffffffu, s, off);
            if (lane >= off) s += t;
        }
        if (lane == 31) wsum[wid] = s;
        __syncthreads();
        if (wid == 0) {
            int ws = wsum[lane];
#pragma unroll
            for (int off = 1; off < 32; off <<= 1) {
                int t = __shfl_up_sync(0xffffffffu, ws, off);
                if (lane >= off) ws += t;
            }
            wsum[lane] = ws;
        }
        __syncthreads();
        int wofs = (wid > 0) ? wsum[wid - 1] : 0;
        int incl = carry_s + wofs + s;
        if (i < n) out[i] = incl - v;
        __syncthreads();
        if (tid == 1023) carry_s = incl;
        __syncthreads();
    }
    if (threadIdx.x == 0) out[n] = carry_s;
}

__global__ void k_fill(const int* __restrict__ src, const int* __restrict__ dst,
                       const int* __restrict__ rowptr, int* __restrict__ cur,
                       int* __restrict__ csr, int E) {
    int e = blockIdx.x * blockDim.x + threadIdx.x;
    if (e >= E) return;
    int d = dst[e];
    int p = rowptr[d] + atomicAdd(&cur[d], 1);
    csr[p] = src[e];
}

// ---------------- aggregation: y_i = nrm_i*(sum_{e->i} nrm_s x_s + nrm_i x_i) ----
template <int NF>
__global__ void k_agg(const float* __restrict__ x, const float* __restrict__ nrm,
                      const int* __restrict__ rowptr, const int* __restrict__ csr,
                      float* __restrict__ y, int N, int F) {
    int warp = (blockIdx.x * blockDim.x + threadIdx.x) >> 5;
    int lane = threadIdx.x & 31;
    if (warp >= N) return;
    int beg = rowptr[warp], end = rowptr[warp + 1];
    float ni = nrm[warp];

    float acc[NF];
#pragma unroll
    for (int j = 0; j < NF; j++) acc[j] = 0.f;

    int e = beg;
    for (; e + 1 < end; e += 2) {
        int s0 = csr[e], s1 = csr[e + 1];
        float n0 = nrm[s0], n1 = nrm[s1];
        const float* x0 = x + (size_t)s0 * F;
        const float* x1 = x + (size_t)s1 * F;
#pragma unroll
        for (int j = 0; j < NF; j++) {
            int f = lane + 32 * j;
            if (f < F) acc[j] += x0[f] * n0 + x1[f] * n1;
        }
    }
    if (e < end) {
        int s0 = csr[e];
        float n0 = nrm[s0];
        const float* x0 = x + (size_t)s0 * F;
#pragma unroll
        for (int j = 0; j < NF; j++) {
            int f = lane + 32 * j;
            if (f < F) acc[j] += x0[f] * n0;
        }
    }
    const float* xi = x + (size_t)warp * F;
    float* yi = y + (size_t)warp * F;
#pragma unroll
    for (int j = 0; j < NF; j++) {
        int f = lane + 32 * j;
        if (f < F) yi[f] = ni * (acc[j] + ni * xi[f]);
    }
}

// float4 variant for F % 4 == 0 (F4 = F/4, NJ = ceil(F4/32))
template <int NJ>
__global__ void k_agg4(const float4* __restrict__ x, const float* __restrict__ nrm,
                       const int* __restrict__ rowptr, const int* __restrict__ csr,
                       float4* __restrict__ y, int N, int F4) {
    int warp = (blockIdx.x * blockDim.x + threadIdx.x) >> 5;
    int lane = threadIdx.x & 31;
    if (warp >= N) return;
    int beg = rowptr[warp], end = rowptr[warp + 1];
    float ni = nrm[warp];

    float4 acc[NJ];
#pragma unroll
    for (int j = 0; j < NJ; j++) acc[j] = make_float4(0.f, 0.f, 0.f, 0.f);

    int e = beg;
    for (; e + 1 < end; e += 2) {
        int s0 = csr[e], s1 = csr[e + 1];
        float n0 = nrm[s0], n1 = nrm[s1];
        const float4* x0 = x + (size_t)s0 * F4;
        const float4* x1 = x + (size_t)s1 * F4;
#pragma unroll
        for (int j = 0; j < NJ; j++) {
            int f = lane + 32 * j;
            if (f < F4) {
                float4 v0 = x0[f], v1 = x1[f];
                acc[j].x += v0.x * n0 + v1.x * n1;
                acc[j].y += v0.y * n0 + v1.y * n1;
                acc[j].z += v0.z * n0 + v1.z * n1;
                acc[j].w += v0.w * n0 + v1.w * n1;
            }
        }
    }
    if (e < end) {
        int s0 = csr[e];
        float n0 = nrm[s0];
        const float4* x0 = x + (size_t)s0 * F4;
#pragma unroll
        for (int j = 0; j < NJ; j++) {
            int f = lane + 32 * j;
            if (f < F4) {
                float4 v0 = x0[f];
                acc[j].x += v0.x * n0;
                acc[j].y += v0.y * n0;
                acc[j].z += v0.z * n0;
                acc[j].w += v0.w * n0;
            }
        }
    }
    const float4* xi = x + (size_t)warp * F4;
    float4* yi = y + (size_t)warp * F4;
#pragma unroll
    for (int j = 0; j < NJ; j++) {
        int f = lane + 32 * j;
        if (f < F4) {
            float4 v = xi[f];
            float4 o;
            o.x = ni * (acc[j].x + ni * v.x);
            o.y = ni * (acc[j].y + ni * v.y);
            o.z = ni * (acc[j].z + ni * v.z);
            o.w = ni * (acc[j].w + ni * v.w);
            yi[f] = o;
        }
    }
}

static void launch_agg(const float* x, const float* nrm, const int* rp, const int* csr,
                       float* y, int N, int F) {
    int blocks = gdiv(N, 8);
    if ((F & 3) == 0) {
        int F4 = F >> 2;
        int nj = gdiv(F4, 32);
        if (nj == 1)      k_agg4<1><<<blocks, 256>>>((const float4*)x, nrm, rp, csr, (float4*)y, N, F4);
        else if (nj == 2) k_agg4<2><<<blocks, 256>>>((const float4*)x, nrm, rp, csr, (float4*)y, N, F4);
        else              k_agg4<3><<<blocks, 256>>>((const float4*)x, nrm, rp, csr, (float4*)y, N, F4);
        return;
    }
    int nf = gdiv(F, 32);
    switch (nf) {
        case 2: k_agg<2><<<blocks, 256>>>(x, nrm, rp, csr, y, N, F); break;
        case 3: k_agg<3><<<blocks, 256>>>(x, nrm, rp, csr, y, N, F); break;
        case 4: k_agg<4><<<blocks, 256>>>(x, nrm, rp, csr, y, N, F); break;
        case 5: k_agg<5><<<blocks, 256>>>(x, nrm, rp, csr, y, N, F); break;
        default: k_agg<8><<<blocks, 256>>>(x, nrm, rp, csr, y, N, F); break;
    }
}

// ---------------- mean pool over contiguous per-graph ranges ----------------
__global__ void k_pool(const float* __restrict__ x, const int* __restrict__ gptr,
                       float* __restrict__ pool, int F) {
    int g = blockIdx.x;
    int beg = gptr[g], end = gptr[g + 1];
    float inv = 1.f / fmaxf((float)(end - beg), 1.f);
    for (int f = threadIdx.x; f < F; f += blockDim.x) {
        float s0 = 0.f, s1 = 0.f, s2 = 0.f, s3 = 0.f;
        int i = beg;
        for (; i + 3 < end; i += 4) {
            s0 += x[(size_t)(i + 0) * F + f];
            s1 += x[(size_t)(i + 1) * F + f];
            s2 += x[(size_t)(i + 2) * F + f];
            s3 += x[(size_t)(i + 3) * F + f];
        }
        for (; i < end; i++) s0 += x[(size_t)i * F + f];
        pool[(size_t)g * F + f] = (s0 + s1 + s2 + s3) * inv;
    }
}

// ---------------- SGEMM 128x128x8, double-buffered, quadrant micro-tile ---------
// C[N,M] = A[N,K] @ W[K,M] (+bias, opt relu), C has leading dim ldc
#define BM 128
#define BN 128
#define BKK 8

__global__ __launch_bounds__(256) void k_sgemm(
    const float* __restrict__ A, const float* __restrict__ W,
    const float* __restrict__ bias, float* __restrict__ C,
    int N, int K, int M, int ldc, int relu)
{
    __shared__ float As[2][BKK][BM];
    __shared__ float Bs[2][BKK][BN];

    int tid = threadIdx.x;
    int row0 = blockIdx.y * BM;
    int col0 = blockIdx.x * BN;
    int tx = tid & 15;         // 0..15
    int ty = tid >> 4;         // 0..15

    // global load mapping
    int a_r = tid >> 1;            // 0..127
    int a_k = (tid & 1) * 4;       // 0 or 4
    int b_k = tid >> 5;            // 0..7
    int b_c = (tid & 31) * 4;      // 0..124

    int ar = row0 + a_r;
    const float* Arow = A + (size_t)(ar < N ? ar : 0) * K;
    bool a_ok = (ar < N);

    float acc[8][8];
#pragma unroll
    for (int i = 0; i < 8; i++)
#pragma unroll
        for (int j = 0; j < 8; j++) acc[i][j] = 0.f;

    float ra[4], rb[4];
    int kt = (K + BKK - 1) / BKK;

    // load tile 0
#pragma unroll
    for (int i = 0; i < 4; i++) {
        int kc = a_k + i;
        ra[i] = (a_ok && kc < K) ? Arow[kc] : 0.f;
    }
#pragma unroll
    for (int i = 0; i < 4; i++) {
        int bc = col0 + b_c + i;
        rb[i] = (b_k < K && bc < M) ? W[(size_t)b_k * M + bc] : 0.f;
    }
#pragma unroll
    for (int i = 0; i < 4; i++) As[0][a_k + i][a_r] = ra[i];
#pragma unroll
    for (int i = 0; i < 4; i++) Bs[0][b_k][b_c + i] = rb[i];
    __syncthreads();

    int buf = 0;
    for (int t = 0; t < kt; t++) {
        int k_next = (t + 1) * BKK;
        if (t + 1 < kt) {
#pragma unroll
            for (int i = 0; i < 4; i++) {
                int kc = k_next + a_k + i;
                ra[i] = (a_ok && kc < K) ? Arow[kc] : 0.f;
            }
            int bk = k_next + b_k;
#pragma unroll
            for (int i = 0; i < 4; i++) {
                int bc = col0 + b_c + i;
                rb[i] = (bk < K && bc < M) ? W[(size_t)bk * M + bc] : 0.f;
            }
        }

#pragma unroll
        for (int kk = 0; kk < BKK; kk++) {
            float af[8], bf[8];
#pragma unroll
            for (int i = 0; i < 4; i++) {
                af[i]     = As[buf][kk][ty * 4 + i];
                af[i + 4] = As[buf][kk][64 + ty * 4 + i];
                bf[i]     = Bs[buf][kk][tx * 4 + i];
                bf[i + 4] = Bs[buf][kk][64 + tx * 4 + i];
            }
#pragma unroll
            for (int i = 0; i < 8; i++)
#pragma unroll
                for (int j = 0; j < 8; j++) acc[i][j] += af[i] * bf[j];
        }

        if (t + 1 < kt) {
            int nb = buf ^ 1;
#pragma unroll
            for (int i = 0; i < 4; i++) As[nb][a_k + i][a_r] = ra[i];
#pragma unroll
            for (int i = 0; i < 4; i++) Bs[nb][b_k][b_c + i] = rb[i];
            __syncthreads();
            buf = nb;
        }
    }

    // epilogue: quadrant layout rows {ty*4+i, 64+ty*4+i}, cols {tx*4+j, 64+tx*4+j}
#pragma unroll
    for (int i = 0; i < 8; i++) {
        int r = row0 + ((i < 4) ? (ty * 4 + i) : (64 + ty * 4 + i - 4));
        if (r >= N) continue;
#pragma unroll
        for (int j = 0; j < 8; j++) {
            int c = col0 + ((j < 4) ? (tx * 4 + j) : (64 + tx * 4 + j - 4));
            if (c >= M) continue;
            float v = acc[i][j] + (bias ? bias[c] : 0.f);
            if (relu) v = fmaxf(v, 0.f);
            C[(size_t)r * ldc + c] = v;
        }
    }
}

static void launch_sgemm(const float* A, const float* W, const float* bias, float* C,
                         int N, int K, int M, int ldc, int relu) {
    dim3 grid(gdiv(M, BN), gdiv(N, BM));
    k_sgemm<<<grid, 256>>>(A, W, bias, C, N, K, M, ldc, relu);
}

// ---------------- branch orchestration ----------------
static void run_branch(const float* x0, const int* ei, int E, const int* bat, int N,
                       int F0, int F1, int F2, int F3,
                       const float* w1, const float* b1,
                       const float* w2, const float* b2,
                       const float* w3, const float* b3,
                       const float* fw1, const float* fb1,
                       const float* fw2, const float* fb2,
                       float* cat_ptr,
                       float* Y, float* A, float* Bf,
                       float* nrm, int* deg, int* cur, int* rowptr, int* csr,
                       int* gcnt, int* gptr, float* pool, float* fc1)
{
    const int* src = ei;
    const int* dst = ei + E;
    const int T = 256;

    k_zero2i<<<gdiv(N, T), T>>>(deg, cur, N);
    k_hist<<<gdiv(E, T), T>>>(dst, deg, E);
    k_scan_ex<<<1, 1024>>>(deg, rowptr, N);
    k_nrm<<<gdiv(N, T), T>>>(deg, nrm, N);
    k_fill<<<gdiv(E, T), T>>>(src, dst, rowptr, cur, csr, E);

    launch_agg(x0, nrm, rowptr, csr, Y, N, F0);
    launch_sgemm(Y, w1, b1, A, N, F0, F1, F1, 1);

    launch_agg(A, nrm, rowptr, csr, Y, N, F1);
    launch_sgemm(Y, w2, b2, Bf, N, F1, F2, F2, 1);

    launch_agg(Bf, nrm, rowptr, csr, Y, N, F2);
    launch_sgemm(Y, w3, b3, A, N, F2, F3, F3, 1);

    k_zeroi<<<1, 256>>>(gcnt, 256);
    k_hist<<<gdiv(N, T), T>>>(bat, gcnt, N);
    k_scan_ex<<<1, 1024>>>(gcnt, gptr, 256);
    k_pool<<<256, 256>>>(A, gptr, pool, F3);

    launch_sgemm(pool, fw1, fb1, fc1, 256, F3, 1024, 1024, 1);
    launch_sgemm(fc1, fw2, fb2, cat_ptr, 256, 1024, 128, 256, 0);
}

extern "C" void kernel_launch(void* const* d_in, const int* in_sizes, int n_in,
                              void* d_out, int out_size)
{
    float *Y, *A, *Bf, *nrm, *pool, *fc1, *cat, *head;
    int *deg, *cur, *rowptr, *csr, *gcnt, *gptr;
    cudaGetSymbolAddress((void**)&Y,      g_Y);
    cudaGetSymbolAddress((void**)&A,      g_A);
    cudaGetSymbolAddress((void**)&Bf,     g_B);
    cudaGetSymbolAddress((void**)&nrm,    g_nrm);
    cudaGetSymbolAddress((void**)&deg,    g_deg);
    cudaGetSymbolAddress((void**)&cur,    g_cur);
    cudaGetSymbolAddress((void**)&rowptr, g_rowptr);
    cudaGetSymbolAddress((void**)&csr,    g_csr);
    cudaGetSymbolAddress((void**)&gcnt,   g_gcnt);
    cudaGetSymbolAddress((void**)&gptr,   g_gptr);
    cudaGetSymbolAddress((void**)&pool,   g_pool);
    cudaGetSymbolAddress((void**)&fc1,    g_fc1);
    cudaGetSymbolAddress((void**)&cat,    g_cat);
    cudaGetSymbolAddress((void**)&head,   g_head);

    const float* mol_x  = (const float*)d_in[0];
    const int*   mol_ei = (const int*)  d_in[1];
    const int*   mol_b  = (const int*)  d_in[2];
    const float* pro_x  = (const float*)d_in[3];
    const int*   pro_ei = (const int*)  d_in[4];
    const int*   pro_b  = (const int*)  d_in[5];

    int N_mol = in_sizes[2];
    int E_mol = in_sizes[1] / 2;
    int F_mol = in_sizes[0] / N_mol;     // 78
    int N_pro = in_sizes[5];
    int E_pro = in_sizes[4] / 2;
    int F_pro = in_sizes[3] / N_pro;     // 54

    const float* mw1  = (const float*)d_in[6];
    const float* mb1  = (const float*)d_in[7];
    const float* mw2  = (const float*)d_in[8];
    const float* mb2  = (const float*)d_in[9];
    const float* mw3  = (const float*)d_in[10];
    const float* mb3  = (const float*)d_in[11];
    const float* mfw1 = (const float*)d_in[12];
    const float* mfb1 = (const float*)d_in[13];
    const float* mfw2 = (const float*)d_in[14];
    const float* mfb2 = (const float*)d_in[15];
    const float* pw1  = (const float*)d_in[16];
    const float* pb1  = (const float*)d_in[17];
    const float* pw2  = (const float*)d_in[18];
    const float* pb2  = (const float*)d_in[19];
    const float* pw3  = (const float*)d_in[20];
    const float* pb3  = (const float*)d_in[21];
    const float* pfw1 = (const float*)d_in[22];
    const float* pfb1 = (const float*)d_in[23];
    const float* pfw2 = (const float*)d_in[24];
    const float* pfb2 = (const float*)d_in[25];
    const float* fc1w = (const float*)d_in[26];
    const float* fc1b = (const float*)d_in[27];
    const float* fc2w = (const float*)d_in[28];
    const float* fc2b = (const float*)d_in[29];
    const float* outw = (const float*)d_in[30];
    const float* outb = (const float*)d_in[31];

    // protein branch (heavy): 54 -> 54 -> 108 -> 216; cat[:,128:256]
    run_branch(pro_x, pro_ei, E_pro, pro_b, N_pro,
               F_pro, F_pro, 2 * F_pro, 4 * F_pro,
               pw1, pb1, pw2, pb2, pw3, pb3,
               pfw1, pfb1, pfw2, pfb2,
               cat + 128,
               Y, A, Bf, nrm, deg, cur, rowptr, csr, gcnt, gptr, pool, fc1);

    // molecule branch: 78 -> 78 -> 156 -> 312; cat[:,0:128]
    run_branch(mol_x, mol_ei, E_mol, mol_b, N_mol,
               F_mol, F_mol, 2 * F_mol, 4 * F_mol,
               mw1, mb1, mw2, mb2, mw3, mb3,
               mfw1, mfb1, mfw2, mfb2,
               cat,
               Y, A, Bf, nrm, deg, cur, rowptr, csr, gcnt, gptr, pool, fc1);

    // combined head
    launch_sgemm(cat,  fc1w, fc1b, fc1,           256, 256,  1024, 1024, 1);
    launch_sgemm(fc1,  fc2w, fc2b, head,          256, 1024, 512,  512,  1);
    launch_sgemm(head, outw, outb, (float*)d_out, 256, 512,  1,    1,    0);
}